// round 1
// baseline (speedup 1.0000x reference)
#include <cuda_runtime.h>
#include <cstdint>

// ---------------------------------------------------------------------------
// ContrastiveLoss: scores[b,c] = sum_r max_{w < s_l[c]} <A[b,r,:], S[c,w,:]> / (obj[b]+eps)
// done twice (im/s and pred/s_pred), summed, then hinge loss.
// Round-0 implementation: fused SIMT fp32 SGEMM (128x128x16 tile, 8x8 micro)
// with max/sum epilogue via shuffle + atomicAdd.
// ---------------------------------------------------------------------------

namespace {
constexpr int BM  = 128;
constexpr int BN  = 128;
constexpr int BK  = 16;
constexpr int TM  = 8;
constexpr int TN  = 8;
constexpr int NTH = 256;
constexpr int LDA = 132;  // padded smem row stride (floats) to reduce STS conflicts
}

__device__ float g_scores[128 * 128];
__device__ float g_loss;

__global__ void zero_scores_kernel(int n) {
    int i = blockIdx.x * blockDim.x + threadIdx.x;
    if (i < n) g_scores[i] = 0.0f;
}

// A: [Bsz, R, d] flattened to M=Bsz*R rows. Bm: [Bsz, W, d].
// Tile cols cover BN/WPAD captions, WPAD (pow2 >= W) padded words each.
__global__ void __launch_bounds__(NTH, 2)
xattn_kernel(const float* __restrict__ A, const float* __restrict__ Bm,
             const int* __restrict__ cap_lens, const int* __restrict__ obj_nums,
             int M, int R, int W, int WPAD, int d, int Bsz)
{
    __shared__ float as[2][BK][LDA];
    __shared__ float bs[2][BK][LDA];

    const int tid   = threadIdx.x;
    const int m0    = blockIdx.x * BM;
    const int cbase = blockIdx.y * (BN / WPAD);

    // ---- loader mapping: 256 threads load 128 rows x 16 k per matrix (2 float4 each)
    const int lrow = tid >> 2;        // 0..63
    const int lk   = (tid & 3) * 4;   // 0,4,8,12

    const int arow0 = m0 + lrow;
    const int arow1 = m0 + lrow + 64;
    const bool av0 = arow0 < M;
    const bool av1 = arow1 < M;
    const float* aptr0 = A + (size_t)arow0 * d + lk;
    const float* aptr1 = A + (size_t)arow1 * d + lk;

    const int n0 = lrow;
    const int n1 = lrow + 64;
    const int c0 = cbase + n0 / WPAD;
    const int w0 = n0 % WPAD;
    const int c1 = cbase + n1 / WPAD;
    const int w1 = n1 % WPAD;
    const bool bv0 = (w0 < W);
    const bool bv1 = (w1 < W);
    const float* bptr0 = Bm + ((size_t)c0 * W + w0) * d + lk;
    const float* bptr1 = Bm + ((size_t)c1 * W + w1) * d + lk;

    const int ty = tid >> 4;   // 0..15
    const int tx = tid & 15;   // 0..15

    float acc[TM][TN];
#pragma unroll
    for (int i = 0; i < TM; i++)
#pragma unroll
        for (int j = 0; j < TN; j++) acc[i][j] = 0.0f;

    float4 ra0, ra1, rb0, rb1;
    const float4 fz = make_float4(0.f, 0.f, 0.f, 0.f);

    // prefetch stage 0
    {
        ra0 = av0 ? *(const float4*)(aptr0) : fz;
        ra1 = av1 ? *(const float4*)(aptr1) : fz;
        rb0 = bv0 ? *(const float4*)(bptr0) : fz;
        rb1 = bv1 ? *(const float4*)(bptr1) : fz;
#pragma unroll
        for (int i = 0; i < 4; i++) {
            as[0][lk + i][lrow]      = (&ra0.x)[i];
            as[0][lk + i][lrow + 64] = (&ra1.x)[i];
            bs[0][lk + i][lrow]      = (&rb0.x)[i];
            bs[0][lk + i][lrow + 64] = (&rb1.x)[i];
        }
    }
    __syncthreads();

    const int nIter = d / BK;
    for (int t = 0; t < nIter; t++) {
        const int buf = t & 1;
        if (t + 1 < nIter) {
            const int off = (t + 1) * BK;
            ra0 = av0 ? *(const float4*)(aptr0 + off) : fz;
            ra1 = av1 ? *(const float4*)(aptr1 + off) : fz;
            rb0 = bv0 ? *(const float4*)(bptr0 + off) : fz;
            rb1 = bv1 ? *(const float4*)(bptr1 + off) : fz;
        }
#pragma unroll
        for (int k = 0; k < BK; k++) {
            float a[TM], b[TN];
            *(float4*)&a[0] = *(const float4*)&as[buf][k][ty * TM];
            *(float4*)&a[4] = *(const float4*)&as[buf][k][ty * TM + 4];
            *(float4*)&b[0] = *(const float4*)&bs[buf][k][tx * TN];
            *(float4*)&b[4] = *(const float4*)&bs[buf][k][tx * TN + 4];
#pragma unroll
            for (int i = 0; i < TM; i++)
#pragma unroll
                for (int j = 0; j < TN; j++) acc[i][j] += a[i] * b[j];
        }
        if (t + 1 < nIter) {
            const int nb = buf ^ 1;
#pragma unroll
            for (int i = 0; i < 4; i++) {
                as[nb][lk + i][lrow]      = (&ra0.x)[i];
                as[nb][lk + i][lrow + 64] = (&ra1.x)[i];
                bs[nb][lk + i][lrow]      = (&rb0.x)[i];
                bs[nb][lk + i][lrow + 64] = (&rb1.x)[i];
            }
        }
        __syncthreads();
    }

    // ---- epilogue: per-row masked max over one caption's words, then atomic sum
    const int G  = WPAD / TN;           // threads per caption group (8 for WPAD=64, 4 for 32)
    const int c  = cbase + tx / G;      // caption handled by this thread
    const int cl = cap_lens[c];         // 1..W
    const int wb = (tx & (G - 1)) * TN; // this thread's first word index

    float rowmax[TM];
#pragma unroll
    for (int i = 0; i < TM; i++) {
        float mx = -1e30f;
#pragma unroll
        for (int j = 0; j < TN; j++)
            if (wb + j < cl) mx = fmaxf(mx, acc[i][j]);
        for (int off = G >> 1; off > 0; off >>= 1)
            mx = fmaxf(mx, __shfl_xor_sync(0xffffffffu, mx, off));
        rowmax[i] = mx;
    }

    if ((tx & (G - 1)) == 0) {
#pragma unroll
        for (int i = 0; i < TM; i++) {
            const int row = m0 + ty * TM + i;
            if (row < M) {
                const int b = row / R;
                const float denom = (float)obj_nums[b] + 1e-6f;
                atomicAdd(&g_scores[b * Bsz + c], rowmax[i] / denom);
            }
        }
    }
}

__global__ void loss_kernel(int Bsz) {
    __shared__ float diag[128];
    __shared__ float red[256];
    const int tid = threadIdx.x;
    for (int i = tid; i < Bsz; i += blockDim.x)
        diag[i] = g_scores[i * Bsz + i];
    __syncthreads();

    float sum = 0.0f;
    const int n = Bsz * Bsz;
    for (int idx = tid; idx < n; idx += blockDim.x) {
        const int i = idx / Bsz;
        const int j = idx - i * Bsz;
        if (i != j) {
            const float sc = g_scores[idx];
            sum += fmaxf(0.0f, 0.2f + sc - diag[i]);   // cost_s
            sum += fmaxf(0.0f, 0.2f + sc - diag[j]);   // cost_im
        }
    }
    red[tid] = sum;
    __syncthreads();
    for (int s = 128; s > 0; s >>= 1) {
        if (tid < s) red[tid] += red[tid + s];
        __syncthreads();
    }
    if (tid == 0) g_loss = red[0];
}

// Output layout: assume tuple order (loss, scores) -> [loss, scores row-major].
// Robust to out_size == B*B (scores only) and out_size == 1 (loss only).
__global__ void write_out_kernel(float* out, int out_size, int n) {
    const int i = blockIdx.x * blockDim.x + threadIdx.x;
    if (i >= out_size) return;
    if (out_size == n) { out[i] = g_scores[i]; return; }
    if (out_size == 1) { out[0] = g_loss; return; }
    if (i == 0) { out[0] = g_loss; return; }
    const int j = i - 1;
    out[i] = (j < n) ? g_scores[j] : 0.0f;
}

extern "C" void kernel_launch(void* const* d_in, const int* in_sizes, int n_in,
                              void* d_out, int out_size) {
    const float* im    = (const float*)d_in[0];
    const int*   im_l  = (const int*)  d_in[1];
    const float* s     = (const float*)d_in[2];
    const int*   s_l   = (const int*)  d_in[3];
    const float* pred  = (const float*)d_in[4];
    const int*   pr_l  = (const int*)  d_in[5];
    const float* sp    = (const float*)d_in[6];
    const int*   sp_l  = (const int*)  d_in[7];

    const int Bsz = in_sizes[1];           // 128
    const int d   = 1024;
    const int R   = in_sizes[0] / (Bsz * d);   // 36
    const int W   = in_sizes[2] / (Bsz * d);   // 50
    const int Rp  = in_sizes[4] / (Bsz * d);   // 25
    const int Wp  = in_sizes[6] / (Bsz * d);   // 30

    auto wpad = [](int w) { int p = 8; while (p < w) p <<= 1; return p; };
    const int W1 = wpad(W);    // 64
    const int W2 = wpad(Wp);   // 32

    zero_scores_kernel<<<(Bsz * Bsz + 255) / 256, 256>>>(Bsz * Bsz);

    const int M1 = Bsz * R;    // 4608
    const int M2 = Bsz * Rp;   // 3200
    dim3 g1((M1 + BM - 1) / BM, Bsz / (BN / W1));   // (36, 64)
    xattn_kernel<<<g1, NTH>>>(im, s, s_l, im_l, M1, R, W, W1, d, Bsz);
    dim3 g2((M2 + BM - 1) / BM, Bsz / (BN / W2));   // (25, 32)
    xattn_kernel<<<g2, NTH>>>(pred, sp, sp_l, pr_l, M2, Rp, Wp, W2, d, Bsz);

    loss_kernel<<<1, 256>>>(Bsz);
    write_out_kernel<<<(out_size + 255) / 256, 256>>>((float*)d_out, out_size, Bsz * Bsz);
}

// round 3
// speedup vs baseline: 2.4857x; 2.4857x over previous
#include <cuda_runtime.h>
#include <cstdint>

// ============================================================================
// ContrastiveLoss via warp-level mma.sync tf32 (sm_100 base target — no
// tcgen05, it's rejected by the compute_100 PTX target this harness uses).
// scores[b,c] = sum_r max_{w<cl[c]} <A[b,r,:], S[c,w,:]> / (obj[b]+1e-6)
// ============================================================================

namespace {
constexpr int D = 1024;
constexpr int BM = 128;
constexpr int BK = 32;                 // k per smem chunk
constexpr int NCHUNK = D / BK;         // 32
constexpr int LDS_STRIDE = 36;         // floats per smem row (conflict-free frags)
constexpr int STAGE_FLOATS = BM * LDS_STRIDE;   // 4608
constexpr int SMEM_FLOATS = 4 * STAGE_FLOATS;   // A0 A1 B0 B1 = 73728 B
}

__device__ float g_scores[128 * 128];
__device__ float g_loss;

__global__ void zero_kernel(int n) {
    int i = blockIdx.x * blockDim.x + threadIdx.x;
    if (i < n) g_scores[i] = 0.0f;
    if (i == 0) g_loss = 0.0f;
}

__device__ __forceinline__ uint32_t f2tf32(float x) {
    uint32_t r;
    asm("cvt.rn.tf32.f32 %0, %1;" : "=r"(r) : "f"(x));
    return r;
}
__device__ __forceinline__ uint4 cvt4(float4 v) {
    return make_uint4(f2tf32(v.x), f2tf32(v.y), f2tf32(v.z), f2tf32(v.w));
}
__device__ __forceinline__ void mma_tf32(float* c, const uint32_t* a, const uint32_t* b) {
    asm volatile(
        "mma.sync.aligned.m16n8k8.row.col.f32.tf32.tf32.f32 "
        "{%0,%1,%2,%3}, {%4,%5,%6,%7}, {%8,%9}, {%0,%1,%2,%3};"
        : "+f"(c[0]), "+f"(c[1]), "+f"(c[2]), "+f"(c[3])
        : "r"(a[0]), "r"(a[1]), "r"(a[2]), "r"(a[3]), "r"(b[0]), "r"(b[1]));
}

// A: [Bsz, R, D] -> M = Bsz*R rows (multiple of 128). Bm: [Bsz, W, D].
// CTA tile: 128 rows x 128 cols; cols = (128/WPAD) captions padded to WPAD words.
template <int WPAD>
__global__ void __launch_bounds__(256, 2)
xattn_mma_kernel(const float* __restrict__ A, const float* __restrict__ Bm,
                 const int* __restrict__ cap_lens, const int* __restrict__ obj_nums,
                 int R, int W, int Bsz)
{
    constexpr int LOGW = (WPAD == 64) ? 6 : 5;
    constexpr int CAPS_PER_TILE = 128 / WPAD;
    constexpr int CAPS_PER_WARP = 64 / WPAD;     // 1 or 2

    extern __shared__ float sm[];
    float* const As[2] = { sm,                    sm + STAGE_FLOATS };
    float* const Bs[2] = { sm + 2 * STAGE_FLOATS, sm + 3 * STAGE_FLOATS };

    const int tid  = threadIdx.x;
    const int wid  = tid >> 5;
    const int lane = tid & 31;
    const int g = lane >> 2;          // group id (0..7)
    const int t = lane & 3;           // thread-in-group (0..3)
    const int wm = wid & 3;           // warp m index (rows wm*32..)
    const int wn = wid >> 2;          // warp n index (cols wn*64..)
    const int m0 = blockIdx.x * BM;
    const int cbase = blockIdx.y * CAPS_PER_TILE;

    // ---- loader mapping: 4 threads per row over k; rows lr and lr+64
    const int lr = tid >> 2;          // 0..63
    const int lk = (tid & 3) << 2;    // 0,4,8,12
    const float* ga0 = A + (size_t)(m0 + lr) * D + lk;
    const float* ga1 = ga0 + (size_t)64 * D;

    const int br0 = lr, br1 = lr + 64;
    const int c0 = cbase + (br0 >> LOGW), w0 = br0 & (WPAD - 1);
    const int c1 = cbase + (br1 >> LOGW), w1 = br1 & (WPAD - 1);
    const bool v0 = (w0 < W), v1 = (w1 < W);
    const float* gb0 = Bm + ((size_t)c0 * W + w0) * D + lk;
    const float* gb1 = Bm + ((size_t)c1 * W + w1) * D + lk;

    const int sa0 = lr * LDS_STRIDE + lk;
    const int sa1 = (lr + 64) * LDS_STRIDE + lk;

    float acc[2][8][4];
#pragma unroll
    for (int mt = 0; mt < 2; mt++)
#pragma unroll
        for (int nt = 0; nt < 8; nt++)
#pragma unroll
            for (int e = 0; e < 4; e++) acc[mt][nt][e] = 0.0f;

    const float4 fz = make_float4(0.f, 0.f, 0.f, 0.f);
    float4 ra[2][2], rb[2][2];

    auto load_regs = [&](int k0) {
        ra[0][0] = *(const float4*)(ga0 + k0);
        ra[0][1] = *(const float4*)(ga0 + k0 + 16);
        ra[1][0] = *(const float4*)(ga1 + k0);
        ra[1][1] = *(const float4*)(ga1 + k0 + 16);
        rb[0][0] = v0 ? *(const float4*)(gb0 + k0)      : fz;
        rb[0][1] = v0 ? *(const float4*)(gb0 + k0 + 16) : fz;
        rb[1][0] = v1 ? *(const float4*)(gb1 + k0)      : fz;
        rb[1][1] = v1 ? *(const float4*)(gb1 + k0 + 16) : fz;
    };
    auto store_smem = [&](int buf) {
        *(uint4*)(As[buf] + sa0)      = cvt4(ra[0][0]);
        *(uint4*)(As[buf] + sa0 + 16) = cvt4(ra[0][1]);
        *(uint4*)(As[buf] + sa1)      = cvt4(ra[1][0]);
        *(uint4*)(As[buf] + sa1 + 16) = cvt4(ra[1][1]);
        *(uint4*)(Bs[buf] + sa0)      = cvt4(rb[0][0]);
        *(uint4*)(Bs[buf] + sa0 + 16) = cvt4(rb[0][1]);
        *(uint4*)(Bs[buf] + sa1)      = cvt4(rb[1][0]);
        *(uint4*)(Bs[buf] + sa1 + 16) = cvt4(rb[1][1]);
    };

    load_regs(0);
    store_smem(0);
    __syncthreads();

    for (int ch = 0; ch < NCHUNK; ch++) {
        const int buf = ch & 1;
        if (ch + 1 < NCHUNK) load_regs((ch + 1) * BK);

        const uint32_t* as = (const uint32_t*)As[buf] + (wm * 32 + g) * LDS_STRIDE + t;
        const uint32_t* bs = (const uint32_t*)Bs[buf] + (wn * 64 + g) * LDS_STRIDE + t;
#pragma unroll
        for (int ks = 0; ks < 4; ks++) {
            const int ko = ks * 8;
            uint32_t afr[2][4];
#pragma unroll
            for (int mt = 0; mt < 2; mt++) {
                const uint32_t* p = as + mt * (16 * LDS_STRIDE) + ko;
                afr[mt][0] = p[0];
                afr[mt][1] = p[8 * LDS_STRIDE];
                afr[mt][2] = p[4];
                afr[mt][3] = p[8 * LDS_STRIDE + 4];
            }
            uint32_t bfr[8][2];
#pragma unroll
            for (int nt = 0; nt < 8; nt++) {
                const uint32_t* p = bs + nt * (8 * LDS_STRIDE) + ko;
                bfr[nt][0] = p[0];
                bfr[nt][1] = p[4];
            }
#pragma unroll
            for (int mt = 0; mt < 2; mt++)
#pragma unroll
                for (int nt = 0; nt < 8; nt++)
                    mma_tf32(acc[mt][nt], afr[mt], bfr[nt]);
        }

        if (ch + 1 < NCHUNK) store_smem((ch + 1) & 1);
        __syncthreads();
    }

    // ---- epilogue: masked max over caption words, reduce over t-lanes, atomics
    int clv[2];
#pragma unroll
    for (int cap = 0; cap < CAPS_PER_WARP; cap++)
        clv[cap] = cap_lens[cbase + wn * CAPS_PER_WARP + cap];

    float mx[2][2][CAPS_PER_WARP];
#pragma unroll
    for (int mt = 0; mt < 2; mt++)
#pragma unroll
        for (int h = 0; h < 2; h++)
#pragma unroll
            for (int cap = 0; cap < CAPS_PER_WARP; cap++)
                mx[mt][h][cap] = -1e30f;

#pragma unroll
    for (int mt = 0; mt < 2; mt++)
#pragma unroll
        for (int nt = 0; nt < 8; nt++)
#pragma unroll
            for (int e = 0; e < 2; e++) {
                const int wc = nt * 8 + 2 * t + e;            // 0..63 within warp
                const int cap = wc >> LOGW;                   // 0..CAPS_PER_WARP-1
                const int wpos = wc & (WPAD - 1);
                if (wpos < clv[cap]) {
                    mx[mt][0][cap] = fmaxf(mx[mt][0][cap], acc[mt][nt][e]);
                    mx[mt][1][cap] = fmaxf(mx[mt][1][cap], acc[mt][nt][2 + e]);
                }
            }

#pragma unroll
    for (int mt = 0; mt < 2; mt++)
#pragma unroll
        for (int h = 0; h < 2; h++)
#pragma unroll
            for (int cap = 0; cap < CAPS_PER_WARP; cap++) {
                float v = mx[mt][h][cap];
                v = fmaxf(v, __shfl_xor_sync(0xffffffffu, v, 1));
                v = fmaxf(v, __shfl_xor_sync(0xffffffffu, v, 2));
                if (t == 0) {
                    const int row = m0 + wm * 32 + mt * 16 + h * 8 + g;
                    const int b = row / R;
                    const float denom = (float)obj_nums[b] + 1e-6f;
                    const int c = cbase + wn * CAPS_PER_WARP + cap;
                    atomicAdd(&g_scores[b * Bsz + c], __fdividef(v, denom));
                }
            }
}

__global__ void loss_kernel(int Bsz) {
    __shared__ float red[256];
    const int tid = threadIdx.x;
    const int n = Bsz * Bsz;
    float sum = 0.0f;
    for (int idx = blockIdx.x * blockDim.x + tid; idx < n; idx += gridDim.x * blockDim.x) {
        const int i = idx / Bsz;
        const int j = idx - i * Bsz;
        if (i != j) {
            const float sc = g_scores[idx];
            const float di = g_scores[i * Bsz + i];
            const float dj = g_scores[j * Bsz + j];
            sum += fmaxf(0.0f, 0.2f + sc - di);
            sum += fmaxf(0.0f, 0.2f + sc - dj);
        }
    }
    red[tid] = sum;
    __syncthreads();
    for (int s = 128; s > 0; s >>= 1) {
        if (tid < s) red[tid] += red[tid + s];
        __syncthreads();
    }
    if (tid == 0) atomicAdd(&g_loss, red[0]);
}

__global__ void write_out_kernel(float* out, int out_size, int n) {
    const int i = blockIdx.x * blockDim.x + threadIdx.x;
    if (i >= out_size) return;
    if (out_size == n) { out[i] = g_scores[i]; return; }
    if (out_size == 1) { out[0] = g_loss; return; }
    if (i == 0) { out[0] = g_loss; return; }
    const int j = i - 1;
    out[i] = (j < n) ? g_scores[j] : 0.0f;
}

extern "C" void kernel_launch(void* const* d_in, const int* in_sizes, int n_in,
                              void* d_out, int out_size) {
    const float* im   = (const float*)d_in[0];
    const int*   im_l = (const int*)  d_in[1];
    const float* s    = (const float*)d_in[2];
    const int*   s_l  = (const int*)  d_in[3];
    const float* pred = (const float*)d_in[4];
    const int*   pr_l = (const int*)  d_in[5];
    const float* sp   = (const float*)d_in[6];
    const int*   sp_l = (const int*)  d_in[7];

    const int Bsz = in_sizes[1];                 // 128
    const int R   = in_sizes[0] / (Bsz * D);     // 36
    const int W   = in_sizes[2] / (Bsz * D);     // 50
    const int Rp  = in_sizes[4] / (Bsz * D);     // 25
    const int Wp  = in_sizes[6] / (Bsz * D);     // 30

    const size_t smem_bytes = SMEM_FLOATS * sizeof(float);  // 73728
    cudaFuncSetAttribute(xattn_mma_kernel<64>, cudaFuncAttributeMaxDynamicSharedMemorySize, (int)smem_bytes);
    cudaFuncSetAttribute(xattn_mma_kernel<32>, cudaFuncAttributeMaxDynamicSharedMemorySize, (int)smem_bytes);

    zero_kernel<<<(Bsz * Bsz + 255) / 256, 256>>>(Bsz * Bsz);

    const int M1 = Bsz * R;    // 4608
    const int M2 = Bsz * Rp;   // 3200
    // part 1: W=50 -> pad 64, 2 captions per 128-col tile, 64 tiles
    dim3 g1(M1 / BM, (Bsz * 64) / 128);
    xattn_mma_kernel<64><<<g1, 256, smem_bytes>>>(im, s, s_l, im_l, R, W, Bsz);
    // part 2: W=30 -> pad 32, 4 captions per tile, 32 tiles
    dim3 g2(M2 / BM, (Bsz * 32) / 128);
    xattn_mma_kernel<32><<<g2, 256, smem_bytes>>>(pred, sp, sp_l, pr_l, Rp, Wp, Bsz);

    loss_kernel<<<32, 256>>>(Bsz);
    write_out_kernel<<<(out_size + 255) / 256, 256>>>((float*)d_out, out_size, Bsz * Bsz);
}

// round 4
// speedup vs baseline: 3.7508x; 1.5089x over previous
#include <cuda_runtime.h>
#include <cuda_bf16.h>
#include <cstdint>

// ============================================================================
// ContrastiveLoss via warp-level mma.sync bf16 m16n8k16 + ldmatrix.
// (tcgen05 is rejected by the harness's compute_100 base PTX target.)
// scores[b,c] = sum_r max_{w<cl[c]} <A[b,r,:], S[c,w,:]> / (obj[b]+1e-6)
// ============================================================================

namespace {
constexpr int D = 1024;
constexpr int BM = 128;
constexpr int BK = 32;                  // k elems per smem chunk (2 x k16 steps)
constexpr int NCHUNK = D / BK;          // 32
constexpr int SROW = 40;                // bf16 elems per smem row (80 B, conflict-free ldmatrix)
constexpr int STAGE_BYTES = BM * SROW * 2;   // 10240
}

__device__ float g_scores[128 * 128];
__device__ float g_loss;

__global__ void zero_kernel(int n) {
    int i = blockIdx.x * blockDim.x + threadIdx.x;
    if (i < n) g_scores[i] = 0.0f;
    if (i == 0) g_loss = 0.0f;
}

__device__ __forceinline__ uint32_t smem_u32(const void* p) {
    uint32_t a;
    asm("{ .reg .u64 t; cvta.to.shared.u64 t, %1; cvt.u32.u64 %0, t; }" : "=r"(a) : "l"(p));
    return a;
}
__device__ __forceinline__ uint32_t pack_bf16(float lo, float hi) {
    __nv_bfloat162 h = __floats2bfloat162_rn(lo, hi);
    return *reinterpret_cast<uint32_t*>(&h);
}
// pack float4 (k,k+1,k+2,k+3) -> 2 regs of a uint2
__device__ __forceinline__ uint2 pack4(float4 v) {
    return make_uint2(pack_bf16(v.x, v.y), pack_bf16(v.z, v.w));
}
__device__ __forceinline__ void ldsm_x4(uint32_t addr, uint32_t* r) {
    asm volatile("ldmatrix.sync.aligned.m8n8.x4.shared.b16 {%0,%1,%2,%3}, [%4];"
                 : "=r"(r[0]), "=r"(r[1]), "=r"(r[2]), "=r"(r[3]) : "r"(addr));
}
__device__ __forceinline__ void mma_bf16(float* c, const uint32_t* a, const uint32_t* b) {
    asm volatile(
        "mma.sync.aligned.m16n8k16.row.col.f32.bf16.bf16.f32 "
        "{%0,%1,%2,%3}, {%4,%5,%6,%7}, {%8,%9}, {%0,%1,%2,%3};"
        : "+f"(c[0]), "+f"(c[1]), "+f"(c[2]), "+f"(c[3])
        : "r"(a[0]), "r"(a[1]), "r"(a[2]), "r"(a[3]), "r"(b[0]), "r"(b[1]));
}

// A: [Bsz, R, D] -> M = Bsz*R rows (multiple of 128). Bm: [Bsz, W, D].
// CTA tile: 128 rows x 128 cols; cols = (128/WPAD) captions padded to WPAD words.
template <int WPAD>
__global__ void __launch_bounds__(256, 2)
xattn_bf16_kernel(const float* __restrict__ A, const float* __restrict__ Bm,
                  const int* __restrict__ cap_lens, const int* __restrict__ obj_nums,
                  int R, int W, int Bsz)
{
    constexpr int LOGW = (WPAD == 64) ? 6 : 5;
    constexpr int CAPS_PER_TILE = 128 / WPAD;
    constexpr int CAPS_PER_WARP = 64 / WPAD;     // 1 or 2

    // stages: [0]=A0 [1]=A1 [2]=B0 [3]=B1
    __shared__ __align__(16) unsigned char smraw[4][STAGE_BYTES];
    const uint32_t sbase = smem_u32(smraw);

    const int tid  = threadIdx.x;
    const int wid  = tid >> 5;
    const int lane = tid & 31;
    const int g = lane >> 2;
    const int t = lane & 3;
    const int wm = wid & 3;           // warp rows wm*32..
    const int wn = wid >> 2;          // warp cols wn*64..
    const int m0 = blockIdx.x * BM;
    const int cbase = blockIdx.y * CAPS_PER_TILE;

    // ---- loader mapping: 2 threads per row, 16 k-floats each
    const int lr = tid >> 1;                  // 0..127
    const int lk = (tid & 1) << 4;            // 0 or 16
    const float* ga = A + (size_t)(m0 + lr) * D + lk;
    const int bc = cbase + (lr >> LOGW);
    const int bw = lr & (WPAD - 1);
    const bool bvalid = bw < W;
    const float* gb = Bm + ((size_t)bc * W + bw) * D + lk;
    // smem store byte offset within stage
    const int soff = lr * (SROW * 2) + lk * 2;

    float acc[2][8][4];
#pragma unroll
    for (int mt = 0; mt < 2; mt++)
#pragma unroll
        for (int nt = 0; nt < 8; nt++)
#pragma unroll
            for (int e = 0; e < 4; e++) acc[mt][nt][e] = 0.0f;

    // ---- ldmatrix per-lane base byte offsets (within a stage)
    // A x4 (per mt): lanes 0-15 -> rows 0-15 k-bytes 0; lanes 16-31 -> rows 0-15 k-bytes 16
    uint32_t aoff[2];
#pragma unroll
    for (int mt = 0; mt < 2; mt++)
        aoff[mt] = (uint32_t)((wm * 32 + mt * 16 + (lane & 15)) * (SROW * 2) + ((lane >> 4) << 4));
    // B x4 (per nb, 16 cols): n_local = (lane&7) + (lane&16 ? 8 : 0); kb = (lane&8) ? 16 : 0
    uint32_t boff[4];
#pragma unroll
    for (int nb = 0; nb < 4; nb++) {
        const int n_local = (lane & 7) + ((lane & 16) ? 8 : 0);
        const int kb = (lane & 8) ? 16 : 0;
        boff[nb] = (uint32_t)((wn * 64 + nb * 16 + n_local) * (SROW * 2) + kb);
    }

    const float4 fz = make_float4(0.f, 0.f, 0.f, 0.f);
    float4 ra[4], rb[4];

    auto load_regs = [&](int k0) {
#pragma unroll
        for (int i = 0; i < 4; i++) ra[i] = *(const float4*)(ga + k0 + i * 4);
#pragma unroll
        for (int i = 0; i < 4; i++) rb[i] = bvalid ? *(const float4*)(gb + k0 + i * 4) : fz;
    };
    auto store_smem = [&](int buf) {
        uint2 a0 = pack4(ra[0]), a1 = pack4(ra[1]), a2 = pack4(ra[2]), a3 = pack4(ra[3]);
        *(uint4*)(&smraw[buf][soff])          = make_uint4(a0.x, a0.y, a1.x, a1.y);
        *(uint4*)(&smraw[buf][soff + 16])     = make_uint4(a2.x, a2.y, a3.x, a3.y);
        uint2 b0 = pack4(rb[0]), b1 = pack4(rb[1]), b2 = pack4(rb[2]), b3 = pack4(rb[3]);
        *(uint4*)(&smraw[2 + buf][soff])      = make_uint4(b0.x, b0.y, b1.x, b1.y);
        *(uint4*)(&smraw[2 + buf][soff + 16]) = make_uint4(b2.x, b2.y, b3.x, b3.y);
    };

    load_regs(0);
    store_smem(0);
    __syncthreads();

    for (int ch = 0; ch < NCHUNK; ch++) {
        const int buf = ch & 1;
        if (ch + 1 < NCHUNK) load_regs((ch + 1) * BK);

        const uint32_t abase = sbase + buf * STAGE_BYTES;
        const uint32_t bbase = sbase + (2 + buf) * STAGE_BYTES;
#pragma unroll
        for (int ks = 0; ks < 2; ks++) {
            const uint32_t ko = ks * 32;      // 16 bf16 = 32 bytes
            uint32_t afr[2][4];
#pragma unroll
            for (int mt = 0; mt < 2; mt++) ldsm_x4(abase + aoff[mt] + ko, afr[mt]);
            uint32_t bfr[4][4];               // [nb] -> {b0(ntile0),b1(ntile0),b0(nt1),b1(nt1)}
#pragma unroll
            for (int nb = 0; nb < 4; nb++) ldsm_x4(bbase + boff[nb] + ko, bfr[nb]);
#pragma unroll
            for (int mt = 0; mt < 2; mt++)
#pragma unroll
                for (int nt = 0; nt < 8; nt++)
                    mma_bf16(acc[mt][nt], afr[mt], &bfr[nt >> 1][(nt & 1) * 2]);
        }

        if (ch + 1 < NCHUNK) store_smem((ch + 1) & 1);
        __syncthreads();
    }

    // ---- epilogue: masked max over caption words, reduce over t-lanes, atomics
    int clv[2];
#pragma unroll
    for (int cap = 0; cap < CAPS_PER_WARP; cap++)
        clv[cap] = cap_lens[cbase + wn * CAPS_PER_WARP + cap];

    float mx[2][2][CAPS_PER_WARP];
#pragma unroll
    for (int mt = 0; mt < 2; mt++)
#pragma unroll
        for (int h = 0; h < 2; h++)
#pragma unroll
            for (int cap = 0; cap < CAPS_PER_WARP; cap++)
                mx[mt][h][cap] = -1e30f;

#pragma unroll
    for (int mt = 0; mt < 2; mt++)
#pragma unroll
        for (int nt = 0; nt < 8; nt++)
#pragma unroll
            for (int e = 0; e < 2; e++) {
                const int wc = nt * 8 + 2 * t + e;            // 0..63 within warp cols
                const int cap = wc >> LOGW;
                const int wpos = wc & (WPAD - 1);
                if (wpos < clv[cap]) {
                    mx[mt][0][cap] = fmaxf(mx[mt][0][cap], acc[mt][nt][e]);
                    mx[mt][1][cap] = fmaxf(mx[mt][1][cap], acc[mt][nt][2 + e]);
                }
            }

#pragma unroll
    for (int mt = 0; mt < 2; mt++)
#pragma unroll
        for (int h = 0; h < 2; h++)
#pragma unroll
            for (int cap = 0; cap < CAPS_PER_WARP; cap++) {
                float v = mx[mt][h][cap];
                v = fmaxf(v, __shfl_xor_sync(0xffffffffu, v, 1));
                v = fmaxf(v, __shfl_xor_sync(0xffffffffu, v, 2));
                if (t == 0) {
                    const int row = m0 + wm * 32 + mt * 16 + h * 8 + g;
                    const int b = row / R;
                    const float denom = (float)obj_nums[b] + 1e-6f;
                    const int c = cbase + wn * CAPS_PER_WARP + cap;
                    atomicAdd(&g_scores[b * Bsz + c], __fdividef(v, denom));
                }
            }
}

__global__ void loss_kernel(int Bsz) {
    __shared__ float red[256];
    const int tid = threadIdx.x;
    const int n = Bsz * Bsz;
    float sum = 0.0f;
    for (int idx = blockIdx.x * blockDim.x + tid; idx < n; idx += gridDim.x * blockDim.x) {
        const int i = idx / Bsz;
        const int j = idx - i * Bsz;
        if (i != j) {
            const float sc = g_scores[idx];
            const float di = g_scores[i * Bsz + i];
            const float dj = g_scores[j * Bsz + j];
            sum += fmaxf(0.0f, 0.2f + sc - di);
            sum += fmaxf(0.0f, 0.2f + sc - dj);
        }
    }
    red[tid] = sum;
    __syncthreads();
    for (int s = 128; s > 0; s >>= 1) {
        if (tid < s) red[tid] += red[tid + s];
        __syncthreads();
    }
    if (tid == 0) atomicAdd(&g_loss, red[0]);
}

__global__ void write_out_kernel(float* out, int out_size, int n) {
    const int i = blockIdx.x * blockDim.x + threadIdx.x;
    if (i >= out_size) return;
    if (out_size == n) { out[i] = g_scores[i]; return; }
    if (out_size == 1) { out[0] = g_loss; return; }
    if (i == 0) { out[0] = g_loss; return; }
    const int j = i - 1;
    out[i] = (j < n) ? g_scores[j] : 0.0f;
}

extern "C" void kernel_launch(void* const* d_in, const int* in_sizes, int n_in,
                              void* d_out, int out_size) {
    const float* im   = (const float*)d_in[0];
    const int*   im_l = (const int*)  d_in[1];
    const float* s    = (const float*)d_in[2];
    const int*   s_l  = (const int*)  d_in[3];
    const float* pred = (const float*)d_in[4];
    const int*   pr_l = (const int*)  d_in[5];
    const float* sp   = (const float*)d_in[6];
    const int*   sp_l = (const int*)  d_in[7];

    const int Bsz = in_sizes[1];                 // 128
    const int R   = in_sizes[0] / (Bsz * D);     // 36
    const int W   = in_sizes[2] / (Bsz * D);     // 50
    const int Rp  = in_sizes[4] / (Bsz * D);     // 25
    const int Wp  = in_sizes[6] / (Bsz * D);     // 30

    zero_kernel<<<(Bsz * Bsz + 255) / 256, 256>>>(Bsz * Bsz);

    const int M1 = Bsz * R;    // 4608
    const int M2 = Bsz * Rp;   // 3200
    // part 1: W=50 -> pad 64, 2 captions per 128-col tile
    dim3 g1(M1 / BM, (Bsz * 64) / 128);
    xattn_bf16_kernel<64><<<g1, 256>>>(im, s, s_l, im_l, R, W, Bsz);
    // part 2: W=30 -> pad 32, 4 captions per tile
    dim3 g2(M2 / BM, (Bsz * 32) / 128);
    xattn_bf16_kernel<32><<<g2, 256>>>(pred, sp, sp_l, pr_l, Rp, Wp, Bsz);

    loss_kernel<<<32, 256>>>(Bsz);
    write_out_kernel<<<(out_size + 255) / 256, 256>>>((float*)d_out, out_size, Bsz * Bsz);
}